// round 17
// baseline (speedup 1.0000x reference)
#include <cuda_runtime.h>
#include <cuda_fp16.h>
#include <math.h>

// ---------------------------------------------------------------------------
// Fused Haar-DWT -> conv1x1 QKV (fp16 mma, fp32 accum) -> 2x2-window
// channel-attention (ALL tensor-core) -> Haar-IDWT.
// x (8,64,256,256) f32; w_qkv_lh (192,64); w_qkv_m (384,128).
//
// R17: lh attention ported to the R16 tensor-core scheme. Per (band, head):
//   S = Q K^T via 2x mma.m16n8k8 (s padded 4->8), p = ex2(S) packed into the
//   PV A-frag (C layout == A layout), O+sum = 1x mma.m16n8k16 vs Vaug
//   (ones col 4). Swizzle constants per stream from row bit6 (match the
//   proven scalar attn_lh constants). Mid attention unchanged from R16.
// 44.5 KB SMEM, 256 threads, 3 CTAs/SM.
// ---------------------------------------------------------------------------

#define NTH  256
#define STH  264            // sub_t row stride (halves); 132 words == 4 mod 32
#define QPH  36             // qkv row stride (halves, 72B)

#define SUBT_BYTES  (32 * STH * 2)          // 16896
#define QKV_BYTES   (384 * QPH * 2)         // 27648
#define SMEM_BYTES  (SUBT_BYTES + QKV_BYTES)   // 44544

// fp16 qkv swizzle: xor 0 or 4 halves (8B) by row bit6
#define QSW(row)        ((((row) >> 6) & 1) << 2)
#define QIDXH(row, pos) ((row) * QPH + ((pos) ^ QSW(row)))

// fragment-ordered fp16 weight images: tile(M16,K16) x 32 lanes x uint4
__device__ uint4 g_wfrag_lh[12 * 4 * 32];
__device__ uint4 g_wfrag_m [24 * 8 * 32];

__device__ __forceinline__ unsigned pack2(float a, float b) {
    __half2 h = __floats2half2_rn(a, b);   // .x (low) = a
    return *(unsigned*)&h;
}
__device__ __forceinline__ unsigned packh2(__half lo, __half hi) {
    return (unsigned)__half_as_ushort(lo) | ((unsigned)__half_as_ushort(hi) << 16);
}
__device__ __forceinline__ float ex2f(float x) {
    float r; asm("ex2.approx.ftz.f32 %0, %1;" : "=f"(r) : "f"(x)); return r;
}
__device__ __forceinline__ float rcpf(float x) {
    float r; asm("rcp.approx.ftz.f32 %0, %1;" : "=f"(r) : "f"(x)); return r;
}
// packed half2 store at logical (row, pos) = values (pos, pos+1)
__device__ __forceinline__ void stq2(__half* qkv, int row, int pos, float a, float b) {
    *(unsigned*)&qkv[QIDXH(row, pos)] = pack2(a, b);
}

// scale * log2(e)
#define SC2_LH  0.36067376022224085f   // 0.25      * log2(e)
#define SC2_M   0.25505003980080184f   // 0.1767767 * log2(e)

// D += A(16x16,row) * B(16x8,col), fp16 in, fp32 accum
__device__ __forceinline__ void mma16(float* d, const uint4 a, unsigned b0, unsigned b1) {
    asm volatile(
        "mma.sync.aligned.m16n8k16.row.col.f32.f16.f16.f32 "
        "{%0,%1,%2,%3}, {%4,%5,%6,%7}, {%8,%9}, {%0,%1,%2,%3};"
        : "+f"(d[0]), "+f"(d[1]), "+f"(d[2]), "+f"(d[3])
        : "r"(a.x), "r"(a.y), "r"(a.z), "r"(a.w), "r"(b0), "r"(b1));
}
// D += A(16x8,row) * B(8x8,col), fp16 in, fp32 accum
__device__ __forceinline__ void mma8h(float* d, unsigned a0, unsigned a1, unsigned b0) {
    asm volatile(
        "mma.sync.aligned.m16n8k8.row.col.f32.f16.f16.f32 "
        "{%0,%1,%2,%3}, {%4,%5}, {%6}, {%0,%1,%2,%3};"
        : "+f"(d[0]), "+f"(d[1]), "+f"(d[2]), "+f"(d[3])
        : "r"(a0), "r"(a1), "r"(b0));
}

// ---------------------------------------------------------------------------
// prep: fragment-order the weights in fp16.
// ALL rows carry the DWT 0.5; q-rows additionally carry scale*log2e.
// ---------------------------------------------------------------------------
__global__ void prep_weights(const float* __restrict__ w_lh,
                             const float* __restrict__ w_m)
{
    const int i = blockIdx.x * blockDim.x + threadIdx.x;
    const int lane = i & 31;
    const int g = lane >> 2, t = lane & 3;
    if (i < 12 * 4 * 32) {
        const int T = i >> 5;
        const int kk = T & 3, mt = T >> 2;
        const int m = mt * 16 + g, k = kk * 16 + 2 * t;
        const float s = (m < 64) ? (SC2_LH * 0.5f) : 0.5f;
        uint4 v;
        v.x = pack2(s * w_lh[m * 64 + k],           s * w_lh[m * 64 + k + 1]);
        v.y = pack2(s * w_lh[(m + 8) * 64 + k],     s * w_lh[(m + 8) * 64 + k + 1]);
        v.z = pack2(s * w_lh[m * 64 + k + 8],       s * w_lh[m * 64 + k + 9]);
        v.w = pack2(s * w_lh[(m + 8) * 64 + k + 8], s * w_lh[(m + 8) * 64 + k + 9]);
        g_wfrag_lh[T * 32 + lane] = v;
    } else {
        const int j = i - 12 * 4 * 32;
        if (j < 24 * 8 * 32) {
            const int T = j >> 5;
            const int kk = T & 7, mt = T >> 3;
            const int m = mt * 16 + g, k = kk * 16 + 2 * t;
            const float s = (m < 128) ? (SC2_M * 0.5f) : 0.5f;
            uint4 v;
            v.x = pack2(s * w_m[m * 128 + k],           s * w_m[m * 128 + k + 1]);
            v.y = pack2(s * w_m[(m + 8) * 128 + k],     s * w_m[(m + 8) * 128 + k + 1]);
            v.z = pack2(s * w_m[m * 128 + k + 8],       s * w_m[m * 128 + k + 9]);
            v.w = pack2(s * w_m[(m + 8) * 128 + k + 8], s * w_m[(m + 8) * 128 + k + 9]);
            g_wfrag_m[T * 32 + lane] = v;
        }
    }
}

// ---------------------------------------------------------------------------
// lh attention on tensor cores. Warp = window; 8 iterations (band x head).
//  S(16x16) = Q K^T: 2x mma.m16n8k8; p = ex2(S) -> PV A-frag;
//  O = P @ Vaug (ones col 4): 1x mma.m16n8k16; sum at O col 4.
// Swizzle: band0 q/v sw0, k sw4; band1 q/v sw4, k sw0 (row bit6).
// ---------------------------------------------------------------------------
__device__ __forceinline__ void attn_lh_tc(
    const __half* __restrict__ qkv, __half* __restrict__ subt,
    int wi, int lane)
{
    const int g = lane >> 2, t = lane & 3;
    const int p0 = wi * 4;
    const unsigned ONE2 = 0x3C003C00u;      // half2(1,1)

#pragma unroll 1
    for (int it = 0; it < 8; ++it) {
        const int bd = it >> 2;
        const int hd = it & 3;
        const int qb  = bd * 192;
        const int swQ = bd ? 4 : 0;         // q and v streams
        const int swK = bd ? 0 : 4;         // k stream

        // Q A-frag (m16n8k8; s padded 4->8, t>=2 zero)
        unsigned aq0 = 0u, aq1 = 0u;
        unsigned bk0 = 0u, bk1 = 0u;
        if (t < 2) {
            const int colq = (p0 + 2 * t) ^ swQ;
            aq0 = *(const unsigned*)&qkv[(qb + g * 4 + hd) * QPH + colq];
            aq1 = *(const unsigned*)&qkv[(qb + (g + 8) * 4 + hd) * QPH + colq];
            const int colk = (p0 + 2 * t) ^ swK;
            bk0 = *(const unsigned*)&qkv[(qb + 64 + g * 4 + hd) * QPH + colk];
            bk1 = *(const unsigned*)&qkv[(qb + 64 + (g + 8) * 4 + hd) * QPH + colk];
        }
        float s0[4], s1[4];
        s0[0] = s0[1] = s0[2] = s0[3] = 0.f;
        s1[0] = s1[1] = s1[2] = s1[3] = 0.f;
        mma8h(s0, aq0, aq1, bk0);   // d = 0..7
        mma8h(s1, aq0, aq1, bk1);   // d = 8..15

        // p = ex2(S) -> PV A-frag (C layout == A layout)
        uint4 pa;
        pa.x = pack2(ex2f(s0[0]), ex2f(s0[1]));
        pa.y = pack2(ex2f(s0[2]), ex2f(s0[3]));
        pa.z = pack2(ex2f(s1[0]), ex2f(s1[1]));
        pa.w = pack2(ex2f(s1[2]), ex2f(s1[3]));

        // Vaug B-frag (cols: v0..v3, ones, 0,0,0)
        unsigned bv0, bv1;
        if (g < 4) {
            const int col = (p0 + g) ^ swQ;
            const int rb = qb + 128 + hd;
            const int r0 = rb + (2 * t) * 4;
            bv0 = packh2(qkv[r0 * QPH + col], qkv[(r0 + 4) * QPH + col]);
            const int r8 = rb + (2 * t + 8) * 4;
            bv1 = packh2(qkv[r8 * QPH + col], qkv[(r8 + 4) * QPH + col]);
        } else if (g == 4) { bv0 = ONE2; bv1 = ONE2; }
        else               { bv0 = 0u;   bv1 = 0u;   }

        float o[4];
        o[0] = o[1] = o[2] = o[3] = 0.f;
        mma16(o, pa, bv0, bv1);

        // normalize (sum at col 4 = lanes t==2) and store
        const int src = (lane & 0x1C) | 2;
        const float sum0 = __shfl_sync(0xffffffffu, o[0], src);
        const float sum1 = __shfl_sync(0xffffffffu, o[2], src);
        const float i0 = rcpf(sum0);
        const float i1 = rcpf(sum1);
        if (t < 2) {
            const int ch0 = qb + g * 4 + hd;
            const int ch8 = qb + (g + 8) * 4 + hd;
            subt[((2*t)   * 8 + wi) * STH + ch0] = __float2half_rn(o[0] * i0);
            subt[((2*t+1) * 8 + wi) * STH + ch0] = __float2half_rn(o[1] * i0);
            subt[((2*t)   * 8 + wi) * STH + ch8] = __float2half_rn(o[2] * i1);
            subt[((2*t+1) * 8 + wi) * STH + ch8] = __float2half_rn(o[3] * i1);
        }
    }
}

// ---------------------------------------------------------------------------
// mid attention on tensor cores (R16, proven).
// ---------------------------------------------------------------------------
__device__ __forceinline__ void attn_mid_tc(
    const __half* __restrict__ qkv, __half* __restrict__ subt,
    int wi, int lane)
{
    const int g = lane >> 2, t = lane & 3;
    const int p0 = wi * 4;
    const unsigned ONE2 = 0x3C003C00u;      // half2(1,1)

#pragma unroll 1
    for (int hd = 0; hd < 4; ++hd) {
        unsigned aq[2][2], bk[4];
#pragma unroll
        for (int mt = 0; mt < 2; ++mt) {
            const int col = (p0 + 2 * t) ^ (mt ? 4 : 0);
            const int c = mt * 16 + g;
            aq[mt][0] = (t < 2) ? *(const unsigned*)&qkv[(c * 4 + hd) * QPH + col] : 0u;
            aq[mt][1] = (t < 2) ? *(const unsigned*)&qkv[((c + 8) * 4 + hd) * QPH + col] : 0u;
        }
#pragma unroll
        for (int nt = 0; nt < 4; ++nt) {
            const int col = (p0 + 2 * t) ^ ((nt >= 2) ? 4 : 0);
            const int d = nt * 8 + g;
            bk[nt] = (t < 2) ? *(const unsigned*)&qkv[(128 + d * 4 + hd) * QPH + col] : 0u;
        }
        float s[2][4][4];
#pragma unroll
        for (int mt = 0; mt < 2; ++mt)
#pragma unroll
            for (int nt = 0; nt < 4; ++nt) {
                s[mt][nt][0] = s[mt][nt][1] = s[mt][nt][2] = s[mt][nt][3] = 0.f;
                mma8h(s[mt][nt], aq[mt][0], aq[mt][1], bk[nt]);
            }

        uint4 pa[2][2];
#pragma unroll
        for (int mt = 0; mt < 2; ++mt)
#pragma unroll
            for (int kc = 0; kc < 2; ++kc) {
                pa[mt][kc].x = pack2(ex2f(s[mt][2*kc][0]),   ex2f(s[mt][2*kc][1]));
                pa[mt][kc].y = pack2(ex2f(s[mt][2*kc][2]),   ex2f(s[mt][2*kc][3]));
                pa[mt][kc].z = pack2(ex2f(s[mt][2*kc+1][0]), ex2f(s[mt][2*kc+1][1]));
                pa[mt][kc].w = pack2(ex2f(s[mt][2*kc+1][2]), ex2f(s[mt][2*kc+1][3]));
            }

        unsigned bv[2][2];
#pragma unroll
        for (int kc = 0; kc < 2; ++kc) {
            const int col = (p0 + g) ^ (kc ? 4 : 0);
            const int rbase = 256 + (kc * 16) * 4 + hd;
            if (g < 4) {
                const int r0 = rbase + (2 * t) * 4;
                bv[kc][0] = packh2(qkv[r0 * QPH + col],
                                   qkv[(r0 + 4) * QPH + col]);
                const int r8 = rbase + (2 * t + 8) * 4;
                bv[kc][1] = packh2(qkv[r8 * QPH + col],
                                   qkv[(r8 + 4) * QPH + col]);
            } else if (g == 4) {
                bv[kc][0] = ONE2; bv[kc][1] = ONE2;
            } else {
                bv[kc][0] = 0u;   bv[kc][1] = 0u;
            }
        }

        float o[2][4];
#pragma unroll
        for (int mt = 0; mt < 2; ++mt) {
            o[mt][0] = o[mt][1] = o[mt][2] = o[mt][3] = 0.f;
#pragma unroll
            for (int kc = 0; kc < 2; ++kc)
                mma16(o[mt], pa[mt][kc], bv[kc][0], bv[kc][1]);
        }

        const int src = (lane & 0x1C) | 2;
#pragma unroll
        for (int mt = 0; mt < 2; ++mt) {
            const float sum0 = __shfl_sync(0xffffffffu, o[mt][0], src);
            const float sum1 = __shfl_sync(0xffffffffu, o[mt][2], src);
            const float i0 = rcpf(sum0);
            const float i1 = rcpf(sum1);
            if (t < 2) {
                const int ch0 = 64 + (mt * 16 + g) * 4 + hd;
                const int ch8 = ch0 + 32;
                subt[((2*t)   * 8 + wi) * STH + ch0] = __float2half_rn(o[mt][0] * i0);
                subt[((2*t+1) * 8 + wi) * STH + ch0] = __float2half_rn(o[mt][1] * i0);
                subt[((2*t)   * 8 + wi) * STH + ch8] = __float2half_rn(o[mt][2] * i1);
                subt[((2*t+1) * 8 + wi) * STH + ch8] = __float2half_rn(o[mt][3] * i1);
            }
        }
    }
}

// ---------------------------------------------------------------------------
__global__ void __launch_bounds__(NTH, 3)
wavelet_attn_kernel(const float* __restrict__ x,
                    float* __restrict__ y)
{
    extern __shared__ char smem[];
    __half* subt = (__half*)smem;                       // 32 x STH halves
    __half* qkv  = (__half*)(smem + SUBT_BYTES);        // 384 x QPH halves

    const int tid  = threadIdx.x;
    const int wblk = blockIdx.x;       // 0..7
    const int h    = blockIdx.y;       // 0..63
    const int b    = blockIdx.z;       // 0..7

    const int warp = tid >> 5, lane = tid & 31;
    const int g = lane >> 2, t = lane & 3;

    const int xrow0 = 4 * h;
    const int xcol0 = 32 * wblk;
    const float* xb = x + (size_t)(b * 64) * 65536;

    // -------- phase 0: load x (float4), butterfly DWT -> sub_t --------
    {
        const int jq = tid & 7;
        const int ch = (tid >> 3) * 2;
        const float* xcA = xb + (size_t)ch * 65536;
        const float* xcB = xcA + 65536;
        const int col = xcol0 + 4 * jq;
#pragma unroll
        for (int dy = 0; dy < 2; ++dy) {
            const int r0 = xrow0 + 2 * dy;
            const float4 tA = *(const float4*)(xcA + r0 * 256 + col);
            const float4 uA = *(const float4*)(xcA + (r0 + 1) * 256 + col);
            const float4 tB = *(const float4*)(xcB + r0 * 256 + col);
            const float4 uB = *(const float4*)(xcB + (r0 + 1) * 256 + col);
#pragma unroll
            for (int dx = 0; dx < 2; ++dx) {
                const float aA = dx ? tA.z : tA.x, bA = dx ? tA.w : tA.y;
                const float cA = dx ? uA.z : uA.x, dA = dx ? uA.w : uA.y;
                const float aB = dx ? tB.z : tB.x, bB = dx ? tB.w : tB.y;
                const float cB = dx ? uB.z : uB.x, dB = dx ? uB.w : uB.y;
                const float t1A = aA + bA, t2A = cA + dA;
                const float t3A = bA - aA, t4A = dA - cA;
                const float t1B = aB + bB, t2B = cB + dB;
                const float t3B = bB - aB, t4B = dB - cB;
                const int row = (2 * dy + dx) * 8 + jq;
                __half* sr = &subt[row * STH + ch];
                *(unsigned*)&sr[0]   = pack2(t1A + t2A, t1B + t2B);  // 2*ll
                *(unsigned*)&sr[64]  = pack2(t2A - t1A, t2B - t1B);  // 2*lh
                *(unsigned*)&sr[128] = pack2(t3A + t4A, t3B + t4B);  // 2*hl
                *(unsigned*)&sr[192] = pack2(t4A - t3A, t4B - t3B);  // 2*hh
            }
        }
    }
    __syncthreads();

    // ======== fused LOW+HIGH GEMM (one pass over w_lh fragments) ========
    {
        const int wm = warp >> 1, wn = warp & 1;
        float acc[2][3][2][4];
#pragma unroll
        for (int bd = 0; bd < 2; ++bd)
#pragma unroll
            for (int mt = 0; mt < 3; ++mt)
#pragma unroll
                for (int nt = 0; nt < 2; ++nt)
                    acc[bd][mt][nt][0] = acc[bd][mt][nt][1] =
                    acc[bd][mt][nt][2] = acc[bd][mt][nt][3] = 0.f;

#pragma unroll
        for (int kk = 0; kk < 4; ++kk) {
            uint4 af[3];
#pragma unroll
            for (int mt = 0; mt < 3; ++mt)
                af[mt] = g_wfrag_lh[((wm * 3 + mt) * 4 + kk) * 32 + lane];

            unsigned bl[2][2], bh[2][2];
            const int kcol = kk * 16 + 2 * t;
#pragma unroll
            for (int nt = 0; nt < 2; ++nt) {
                const int row = (wn * 2 + nt) * 8 + g;
                const __half* sr = &subt[row * STH + kcol];
                bl[nt][0] = *(const unsigned*)&sr[0];
                bl[nt][1] = *(const unsigned*)&sr[8];
                bh[nt][0] = *(const unsigned*)&sr[192];
                bh[nt][1] = *(const unsigned*)&sr[200];
            }
#pragma unroll
            for (int mt = 0; mt < 3; ++mt)
#pragma unroll
                for (int nt = 0; nt < 2; ++nt) {
                    mma16(acc[0][mt][nt], af[mt], bl[nt][0], bl[nt][1]);
                    mma16(acc[1][mt][nt], af[mt], bh[nt][0], bh[nt][1]);
                }
        }
#pragma unroll
        for (int bd = 0; bd < 2; ++bd)
#pragma unroll
            for (int mt = 0; mt < 3; ++mt) {
                const int m  = bd * 192 + wm * 48 + mt * 16 + g;
                const int p0 = 8 * t + wn * 2;
                stq2(qkv, m,     p0,     acc[bd][mt][0][0], acc[bd][mt][1][0]);
                stq2(qkv, m,     p0 + 4, acc[bd][mt][0][1], acc[bd][mt][1][1]);
                stq2(qkv, m + 8, p0,     acc[bd][mt][0][2], acc[bd][mt][1][2]);
                stq2(qkv, m + 8, p0 + 4, acc[bd][mt][0][3], acc[bd][mt][1][3]);
            }
        __syncthreads();

        attn_lh_tc(qkv, subt, warp, lane);   // tensor-core, all heads+bands
        // no barrier: mid mainloop reads subt cols 64..192 (disjoint);
        // qkv WAR guarded by the barrier before the mid C-store.
    }

    // ======== MID GEMM: w_m @ sub_t[:, 64..192) ========
    {
        float acc[3][4][4];
#pragma unroll
        for (int mt = 0; mt < 3; ++mt)
#pragma unroll
            for (int nt = 0; nt < 4; ++nt)
                acc[mt][nt][0] = acc[mt][nt][1] = acc[mt][nt][2] = acc[mt][nt][3] = 0.f;

#pragma unroll
        for (int kk = 0; kk < 8; ++kk) {
            uint4 af[3];
#pragma unroll
            for (int mt = 0; mt < 3; ++mt)
                af[mt] = g_wfrag_m[((warp * 3 + mt) * 8 + kk) * 32 + lane];

            unsigned bf[4][2];
            const int kcol = 64 + kk * 16 + 2 * t;
#pragma unroll
            for (int nt = 0; nt < 4; ++nt) {
                const __half* sr = &subt[(nt * 8 + g) * STH + kcol];
                bf[nt][0] = *(const unsigned*)&sr[0];
                bf[nt][1] = *(const unsigned*)&sr[8];
            }
#pragma unroll
            for (int mt = 0; mt < 3; ++mt)
#pragma unroll
                for (int nt = 0; nt < 4; ++nt)
                    mma16(acc[mt][nt], af[mt], bf[nt][0], bf[nt][1]);
        }
        __syncthreads();   // all warps done reading qkv (attn_lh_tc) -> C-store

#pragma unroll
        for (int mt = 0; mt < 3; ++mt) {
            const int m  = warp * 48 + mt * 16 + g;
            const int p0 = 8 * t;
            stq2(qkv, m,     p0,     acc[mt][0][0], acc[mt][1][0]);
            stq2(qkv, m,     p0 + 2, acc[mt][2][0], acc[mt][3][0]);
            stq2(qkv, m,     p0 + 4, acc[mt][0][1], acc[mt][1][1]);
            stq2(qkv, m,     p0 + 6, acc[mt][2][1], acc[mt][3][1]);
            stq2(qkv, m + 8, p0,     acc[mt][0][2], acc[mt][1][2]);
            stq2(qkv, m + 8, p0 + 2, acc[mt][2][2], acc[mt][3][2]);
            stq2(qkv, m + 8, p0 + 4, acc[mt][0][3], acc[mt][1][3]);
            stq2(qkv, m + 8, p0 + 6, acc[mt][2][3], acc[mt][3][3]);
        }
        __syncthreads();

        attn_mid_tc(qkv, subt, warp, lane);   // tensor-core, all heads
        __syncthreads();
    }

    // -------- phase 4: butterfly IDWT from sub_t (fp16) -> y --------
    {
        const int jq = tid & 7;
        const int ch = (tid >> 3) * 2;
        float* ycA = y + (size_t)(b * 64 + ch) * 65536;
        float* ycB = ycA + 65536;
        const int col = xcol0 + 4 * jq;
#pragma unroll
        for (int dy = 0; dy < 2; ++dy) {
            float topA[4], botA[4], topB[4], botB[4];
#pragma unroll
            for (int dx = 0; dx < 2; ++dx) {
                const int row = (2 * dy + dx) * 8 + jq;
                const __half* sr = &subt[row * STH + ch];
                const float2 ll = __half22float2(*(const __half2*)&sr[0]);
                const float2 lh = __half22float2(*(const __half2*)&sr[64]);
                const float2 hl = __half22float2(*(const __half2*)&sr[128]);
                const float2 hh = __half22float2(*(const __half2*)&sr[192]);
                const float uA = ll.x + hh.x, wA = lh.x + hl.x;
                const float vA = ll.x - hh.x, zA = hl.x - lh.x;
                const float uB = ll.y + hh.y, wB = lh.y + hl.y;
                const float vB = ll.y - hh.y, zB = hl.y - lh.y;
                topA[2 * dx]     = (uA - wA) * 0.5f;
                topA[2 * dx + 1] = (vA + zA) * 0.5f;
                botA[2 * dx]     = (vA - zA) * 0.5f;
                botA[2 * dx + 1] = (uA + wA) * 0.5f;
                topB[2 * dx]     = (uB - wB) * 0.5f;
                topB[2 * dx + 1] = (vB + zB) * 0.5f;
                botB[2 * dx]     = (vB - zB) * 0.5f;
                botB[2 * dx + 1] = (uB + wB) * 0.5f;
            }
            const int r0 = xrow0 + 2 * dy;
            *(float4*)(ycA + r0 * 256 + col)       = make_float4(topA[0], topA[1], topA[2], topA[3]);
            *(float4*)(ycA + (r0 + 1) * 256 + col) = make_float4(botA[0], botA[1], botA[2], botA[3]);
            *(float4*)(ycB + r0 * 256 + col)       = make_float4(topB[0], topB[1], topB[2], topB[3]);
            *(float4*)(ycB + (r0 + 1) * 256 + col) = make_float4(botB[0], botB[1], botB[2], botB[3]);
        }
    }
}

// ---------------------------------------------------------------------------
extern "C" void kernel_launch(void* const* d_in, const int* in_sizes, int n_in,
                              void* d_out, int out_size)
{
    (void)in_sizes; (void)n_in; (void)out_size;
    const float* x    = (const float*)d_in[0];
    const float* w_lh = (const float*)d_in[1];
    const float* w_m  = (const float*)d_in[2];
    float* y = (float*)d_out;

    cudaFuncSetAttribute(wavelet_attn_kernel,
                         cudaFuncAttributeMaxDynamicSharedMemorySize, SMEM_BYTES);

    prep_weights<<<30, 256>>>(w_lh, w_m);

    dim3 grid(8, 64, 8);   // wblk, h, b -> 4096 CTAs
    wavelet_attn_kernel<<<grid, NTH, SMEM_BYTES>>>(x, y);
}